// round 10
// baseline (speedup 1.0000x reference)
#include <cuda_runtime.h>
#include <math.h>

#define NDIM 542
#define LD   544
#define SZ   (544*544)
#define LDH  320          // half-plane padded width (272 used)
#define NH   272          // 542/2 + 1
#define SZH  (544*320)
#define BB   8
#define CC   3
#define BC   24
#define KS   31
#define PAD  15
#define HREF 512

// ---------------- device scratch ----------------
__device__ __align__(16) float  g_xA[BC*SZ];
__device__ __align__(16) float  g_xB[BC*SZ];
__device__ __align__(16) float2 g_C1[BC*SZH];
__device__ __align__(16) float2 g_C2[BC*SZH];
__device__ __align__(16) float2 g_W[SZ];        // W[v*LD+j] = e^{-2i pi (v*j mod N)/N}, zero pads
__device__ __align__(16) float2 g_Wd[LD*LDH];   // Wd[j*LDH+n] = c_n/N^2 * e^{-2i pi (n*j mod N)/N}, zero pads
__device__ __align__(16) float2 g_Dk[BB*SZH];
__device__ float  g_DgSum[CC*SZH];
__device__ float2 g_Gb[BB*NDIM*KS];
__device__ float2 g_Wt[NDIM];
__device__ float  g_v[BB*2*NDIM];

// ---------------- twiddle tables ----------------
__global__ void k_wt() {
    int m = blockIdx.x*blockDim.x + threadIdx.x;
    if (m >= NDIM) return;
    float ang = (float)(-2.0*3.14159265358979323846/542.0) * (float)m;
    float s, c; sincosf(ang, &s, &c);
    g_Wt[m] = make_float2(c, s);
}

__global__ void k_wm() {
    int gid = blockIdx.x*blockDim.x + threadIdx.x;
    if (gid >= SZ) return;
    int v = gid / LD, j = gid % LD;
    float2 w = make_float2(0.f, 0.f);
    if (v < NDIM && j < NDIM) {
        int m = (v*j) % NDIM;
        float ang = (float)(-2.0*3.14159265358979323846/542.0) * (float)m;
        float s, c; sincosf(ang, &s, &c);
        w = make_float2(c, s);
    }
    g_W[gid] = w;
}

__global__ void k_wd() {
    int gid = blockIdx.x*blockDim.x + threadIdx.x;
    if (gid >= LD*LDH) return;
    int j = gid / LDH, n = gid % LDH;
    float2 w = make_float2(0.f, 0.f);
    if (j < NDIM && n < NH) {
        float cn = (n == 0 || n == NH-1) ? 1.f : 2.f;
        float scale = cn / ((float)NDIM * (float)NDIM);
        int m = (n * j) % NDIM;
        float2 t = g_Wt[m];
        w = make_float2(scale * t.x, scale * t.y);
    }
    g_Wd[gid] = w;
}

// ---------------- edge-replicate pad (fills both ping-pong buffers) ----------------
__global__ void k_pad(const float* __restrict__ y) {
    int gid = blockIdx.x*blockDim.x + threadIdx.x;
    if (gid >= BC*SZ) return;
    int bc = gid / SZ, rem = gid % SZ, i = rem / LD, j = rem % LD;
    float val = 0.f;
    if (i < NDIM && j < NDIM) {
        int si = i - PAD; si = si < 0 ? 0 : (si > HREF-1 ? HREF-1 : si);
        int sj = j - PAD; sj = sj < 0 ? 0 : (sj > HREF-1 ? HREF-1 : sj);
        val = y[bc*HREF*HREF + si*HREF + sj];
    }
    g_xA[gid] = val;
    g_xB[gid] = val;
}

// ---------------- alpha (separable taper) ----------------
__global__ void k_alpha(const float* __restrict__ kptr) {
    int b = blockIdx.x;
    __shared__ float p[2][KS];
    __shared__ float rr[2][KS];
    int t = threadIdx.x; // 64 threads
    if (t < KS) {
        float s = 0.f;
        for (int j = 0; j < KS; j++) s += kptr[b*KS*KS + t*KS + j];
        p[0][t] = s;
    } else if (t >= 32 && t < 32+KS) {
        int c = t - 32; float s = 0.f;
        for (int i = 0; i < KS; i++) s += kptr[b*KS*KS + i*KS + c];
        p[1][c] = s;
    }
    __syncthreads();
    if (t < KS) {
        float s = 0.f;
        for (int n = 0; n + t < KS; n++) s += p[0][n]*p[0][n+t];
        rr[0][t] = s;
    } else if (t >= 32 && t < 32+KS) {
        int m = t - 32; float s = 0.f;
        for (int n = 0; n + m < KS; n++) s += p[1][n]*p[1][n+m];
        rr[1][m] = s;
    }
    __syncthreads();
    for (int i = t; i < NDIM; i += 64) {
        #pragma unroll
        for (int a = 0; a < 2; a++) {
            float z;
            if (i <= 30)                   z = rr[a][i];
            else if (i >= 511 && i <= 540) z = rr[a][541 - i];
            else if (i == 541)             z = rr[a][0];
            else                           z = 0.f;
            g_v[(b*2 + a)*NDIM + i] = 1.f - z / rr[a][0];
        }
    }
}

// ---------------- Dk: two-stage sparse DFT of k (half-plane in v) ----------------
__global__ void k_gb(const float* __restrict__ kptr) {
    int gid = blockIdx.x*blockDim.x + threadIdx.x;
    if (gid >= BB*NDIM*KS) return;
    int b = gid / (NDIM*KS), rem = gid % (NDIM*KS), u = rem / KS, j = rem % KS;
    int idx = (u * 527) % NDIM;
    float2 acc = make_float2(0.f, 0.f);
    for (int i = 0; i < KS; i++) {
        float kv = kptr[b*KS*KS + i*KS + j];
        float2 w = g_Wt[idx];
        acc.x += kv*w.x; acc.y += kv*w.y;
        idx += u; if (idx >= NDIM) idx -= NDIM;
    }
    g_Gb[gid] = acc;
}

__global__ void k_dk() {
    int gid = blockIdx.x*blockDim.x + threadIdx.x;
    if (gid >= BB*NDIM*NH) return;
    int b = gid / (NDIM*NH), rem = gid % (NDIM*NH), u = rem / NH, v = rem % NH;
    int idx = (v * 527) % NDIM;
    const float2* gb = &g_Gb[(b*NDIM + u)*KS];
    float2 acc = make_float2(0.f, 0.f);
    for (int j = 0; j < KS; j++) {
        float2 g = gb[j]; float2 w = g_Wt[idx];
        acc.x += g.x*w.x - g.y*w.y;
        acc.y += g.x*w.y + g.y*w.x;
        idx += v; if (idx >= NDIM) idx -= NDIM;
    }
    g_Dk[b*SZH + u*LDH + v] = acc;
}

// ---------------- DgSum (half-plane) ----------------
__global__ void k_dgsum(const float* __restrict__ filters, const float* __restrict__ lam) {
    int gid = blockIdx.x*blockDim.x + threadIdx.x;
    if (gid >= CC*NDIM*NH) return;
    int c = gid / (NDIM*NH), rem = gid % (NDIM*NH), u = rem / NH, v = rem % NH;
    float2 e[3][3];
    #pragma unroll
    for (int i = 0; i < 3; i++)
        #pragma unroll
        for (int j = 0; j < 3; j++) {
            int m = ((i-1)*u + (j-1)*v) % NDIM;
            if (m < 0) m += NDIM;
            e[i][j] = g_Wt[m];
        }
    float sum = 0.f;
    for (int nf = 0; nf < 8; nf++) {
        const float* f = &filters[(nf*CC + c)*9];
        float ax = 0.f, ay = 0.f;
        #pragma unroll
        for (int i = 0; i < 3; i++)
            #pragma unroll
            for (int j = 0; j < 3; j++) {
                float fv = f[i*3+j];
                ax += fv*e[i][j].x; ay += fv*e[i][j].y;
            }
        sum += ax*ax + ay*ay;
    }
    g_DgSum[c*SZH + u*LDH + v] = expf(lam[0]) * sum;
}

// ---------------- circular conv 31x31 + alpha blend (BAND ONLY) ----------------
__global__ __launch_bounds__(256) void k_conv(int dir, const float* __restrict__ kptr) {
    __shared__ float sk[KS*KS];
    __shared__ float sp[62*62];
    const float* in  = dir ? g_xB : g_xA;
    float*       out = dir ? g_xA : g_xB;
    int bc = blockIdx.z, b = bc / 3;
    int id = blockIdx.x;
    int bx0, by0;
    if (id < 17)      { by0 = 0;                  bx0 = id*32; }
    else if (id < 34) { by0 = 510;                bx0 = (id-17)*32; }
    else if (id < 49) { bx0 = 0;                  by0 = 32 + (id-34)*32; }
    else              { bx0 = 510;                by0 = 32 + (id-49)*32; }

    int tid = threadIdx.y*32 + threadIdx.x;
    for (int idx = tid; idx < KS*KS; idx += 256) sk[idx] = kptr[b*KS*KS + idx];
    const float* inb = in + bc*SZ;
    for (int idx = tid; idx < 62*62; idx += 256) {
        int r = idx / 62, c = idx % 62;
        int gi = by0 - PAD + r; if (gi < 0) gi += NDIM; else if (gi >= NDIM) gi -= NDIM;
        int gj = bx0 - PAD + c; if (gj < 0) gj += NDIM; else if (gj >= NDIM) gj -= NDIM;
        sp[idx] = inb[gi*LD + gj];
    }
    __syncthreads();
    int tx = threadIdx.x, ty = threadIdx.y;
    float acc[4] = {0.f, 0.f, 0.f, 0.f};
    for (int i = 0; i < KS; i++) {
        const float* p0 = &sp[(ty +  0 + 30 - i)*62 + tx + 30];
        const float* p1 = &sp[(ty +  8 + 30 - i)*62 + tx + 30];
        const float* p2 = &sp[(ty + 16 + 30 - i)*62 + tx + 30];
        const float* p3 = &sp[(ty + 24 + 30 - i)*62 + tx + 30];
        const float* pk = &sk[i*KS];
        #pragma unroll
        for (int j = 0; j < KS; j++) {
            float kv = pk[j];
            acc[0] += kv * p0[-j];
            acc[1] += kv * p1[-j];
            acc[2] += kv * p2[-j];
            acc[3] += kv * p3[-j];
        }
    }
    int x = bx0 + tx;
    float v1x = (x < NDIM) ? g_v[(b*2 + 1)*NDIM + x] : 0.f;
    float* outb = out + bc*SZ;
    #pragma unroll
    for (int r = 0; r < 4; r++) {
        int yy = by0 + ty + 8*r;
        if (yy < NDIM && x < NDIM) {
            float a  = g_v[(b*2 + 0)*NDIM + yy] * v1x;
            float c0 = sp[(ty + 8*r + 15)*62 + tx + 15];
            outb[yy*LD + x] = a*c0 + (1.f - a)*acc[r];
        }
    }
}

// ---------------- DFT GEMMs (double-buffered smem, 1 sync/iter) ----------------
#define GBK 16

// pass A: C1[bc][m][n] = sum_k X[bc][m][k] * W[n][k],  n in [0,320)
__global__ __launch_bounds__(256) void k_dft_rows_realin() {
    __shared__ __align__(16) float  sX[2][GBK][64];
    __shared__ __align__(16) float2 sW[2][GBK][64];
    int bc = blockIdx.z, m0 = blockIdx.y*64, n0 = blockIdx.x*64;
    const float* Xb = g_xB + bc*SZ;
    const float* Wf = (const float*)g_W;
    int t = threadIdx.x, tm = t >> 4, tn = t & 15;
    int xr = t >> 2, xq = t & 3;
    int wr0 = t >> 3,        wq0 = t & 7;
    int wr1 = (t+256) >> 3,  wq1 = t & 7;
    float ar[4][4], ai[4][4];
    #pragma unroll
    for (int r = 0; r < 4; r++)
        #pragma unroll
        for (int c = 0; c < 4; c++) { ar[r][c] = 0.f; ai[r][c] = 0.f; }

    // preload tile 0
    {
        float4 v = make_float4(0.f,0.f,0.f,0.f);
        if (m0 + xr < LD) v = *(const float4*)&Xb[(m0+xr)*LD + xq*4];
        sX[0][xq*4+0][xr] = v.x; sX[0][xq*4+1][xr] = v.y; sX[0][xq*4+2][xr] = v.z; sX[0][xq*4+3][xr] = v.w;
        float4 w0 = *(const float4*)&Wf[(n0+wr0)*(2*LD) + wq0*4];   // n0+r < 320 always valid
        sW[0][wq0*2+0][wr0] = make_float2(w0.x, w0.y);
        sW[0][wq0*2+1][wr0] = make_float2(w0.z, w0.w);
        float4 w1 = *(const float4*)&Wf[(n0+wr1)*(2*LD) + wq1*4];
        sW[0][wq1*2+0][wr1] = make_float2(w1.x, w1.y);
        sW[0][wq1*2+1][wr1] = make_float2(w1.z, w1.w);
    }
    __syncthreads();

    const int NIT = LD/GBK;
    for (int it = 0; it < NIT; it++) {
        int p = it & 1;
        float4 xv, w0v, w1v;
        bool pf = (it + 1 < NIT);
        if (pf) {
            int k0 = (it+1)*GBK;
            xv = make_float4(0.f,0.f,0.f,0.f);
            if (m0 + xr < LD) xv = *(const float4*)&Xb[(m0+xr)*LD + k0 + xq*4];
            w0v = *(const float4*)&Wf[(n0+wr0)*(2*LD) + k0*2 + wq0*4];
            w1v = *(const float4*)&Wf[(n0+wr1)*(2*LD) + k0*2 + wq1*4];
        }
        #pragma unroll
        for (int kk = 0; kk < GBK; kk++) {
            float4 a4 = *(const float4*)&sX[p][kk][tm*4];
            float4 wA = *(const float4*)&sW[p][kk][tn*4];
            float4 wB = *(const float4*)&sW[p][kk][tn*4+2];
            float a[4]  = {a4.x, a4.y, a4.z, a4.w};
            float wr[4] = {wA.x, wA.z, wB.x, wB.z};
            float wi[4] = {wA.y, wA.w, wB.y, wB.w};
            #pragma unroll
            for (int r = 0; r < 4; r++)
                #pragma unroll
                for (int c = 0; c < 4; c++) { ar[r][c] += a[r]*wr[c]; ai[r][c] += a[r]*wi[c]; }
        }
        if (pf) {
            int q = 1 - p;
            sX[q][xq*4+0][xr] = xv.x; sX[q][xq*4+1][xr] = xv.y; sX[q][xq*4+2][xr] = xv.z; sX[q][xq*4+3][xr] = xv.w;
            sW[q][wq0*2+0][wr0] = make_float2(w0v.x, w0v.y);
            sW[q][wq0*2+1][wr0] = make_float2(w0v.z, w0v.w);
            sW[q][wq1*2+0][wr1] = make_float2(w1v.x, w1v.y);
            sW[q][wq1*2+1][wr1] = make_float2(w1v.z, w1v.w);
        }
        __syncthreads();
    }
    float2* Ob = g_C1 + bc*SZH;
    #pragma unroll
    for (int r = 0; r < 4; r++)
        #pragma unroll
        for (int c = 0; c < 4; c++) {
            int gm = m0 + tm*4 + r, gn = n0 + tn*4 + c;
            if (gm < LD) Ob[gm*LDH + gn] = make_float2(ar[r][c], ai[r][c]);
        }
}

// pass B (FWD): C2[bc][m][n] = WienerFilter( sum_k W[m][k]*C1[bc][k][n] )   (fused k_pw epilogue)
// pass C (CONJ): C1[bc][m][n] = sum_k conj(W[m][k])*C2[bc][k][n]
template<bool CONJ>
__global__ __launch_bounds__(256) void k_dft_cols() {
    __shared__ __align__(16) float2 sW[2][GBK][64];
    __shared__ __align__(16) float2 sA[2][GBK][64];
    int bc = blockIdx.z, m0 = blockIdx.y*64, n0 = blockIdx.x*64;
    const float2* A = (CONJ ? g_C2 : g_C1) + bc*SZH;
    float2*       O = (CONJ ? g_C1 : g_C2) + bc*SZH;
    const float* Wf = (const float*)g_W;
    const float* Af = (const float*)A;
    int t = threadIdx.x, tm = t >> 4, tn = t & 15;
    int wr0 = t >> 3,        wq0 = t & 7;
    int wr1 = (t+256) >> 3,  wq1 = t & 7;
    int ar0 = t >> 5,        aq0 = t & 31;
    int ar1 = (t+256) >> 5,  aq1 = t & 31;
    float ar[4][4], ai[4][4];
    #pragma unroll
    for (int r = 0; r < 4; r++)
        #pragma unroll
        for (int c = 0; c < 4; c++) { ar[r][c] = 0.f; ai[r][c] = 0.f; }

    // preload tile 0
    {
        float4 w0 = make_float4(0.f,0.f,0.f,0.f);
        if (m0 + wr0 < LD) w0 = *(const float4*)&Wf[(m0+wr0)*(2*LD) + wq0*4];
        if (CONJ) { w0.y = -w0.y; w0.w = -w0.w; }
        sW[0][wq0*2+0][wr0] = make_float2(w0.x, w0.y);
        sW[0][wq0*2+1][wr0] = make_float2(w0.z, w0.w);
        float4 w1 = make_float4(0.f,0.f,0.f,0.f);
        if (m0 + wr1 < LD) w1 = *(const float4*)&Wf[(m0+wr1)*(2*LD) + wq1*4];
        if (CONJ) { w1.y = -w1.y; w1.w = -w1.w; }
        sW[0][wq1*2+0][wr1] = make_float2(w1.x, w1.y);
        sW[0][wq1*2+1][wr1] = make_float2(w1.z, w1.w);
        float4 a0 = *(const float4*)&Af[(ar0)*(2*LDH) + (n0 + aq0*2)*2];
        sA[0][ar0][aq0*2+0] = make_float2(a0.x, a0.y);
        sA[0][ar0][aq0*2+1] = make_float2(a0.z, a0.w);
        float4 a1 = *(const float4*)&Af[(ar1)*(2*LDH) + (n0 + aq1*2)*2];
        sA[0][ar1][aq1*2+0] = make_float2(a1.x, a1.y);
        sA[0][ar1][aq1*2+1] = make_float2(a1.z, a1.w);
    }
    __syncthreads();

    const int NIT = LD/GBK;
    for (int it = 0; it < NIT; it++) {
        int p = it & 1;
        float4 w0v, w1v, a0v, a1v;
        bool pf = (it + 1 < NIT);
        if (pf) {
            int k0 = (it+1)*GBK;
            w0v = make_float4(0.f,0.f,0.f,0.f);
            if (m0 + wr0 < LD) w0v = *(const float4*)&Wf[(m0+wr0)*(2*LD) + k0*2 + wq0*4];
            if (CONJ) { w0v.y = -w0v.y; w0v.w = -w0v.w; }
            w1v = make_float4(0.f,0.f,0.f,0.f);
            if (m0 + wr1 < LD) w1v = *(const float4*)&Wf[(m0+wr1)*(2*LD) + k0*2 + wq1*4];
            if (CONJ) { w1v.y = -w1v.y; w1v.w = -w1v.w; }
            a0v = *(const float4*)&Af[(k0+ar0)*(2*LDH) + (n0 + aq0*2)*2];
            a1v = *(const float4*)&Af[(k0+ar1)*(2*LDH) + (n0 + aq1*2)*2];
        }
        #pragma unroll
        for (int kk = 0; kk < GBK; kk++) {
            float4 wA = *(const float4*)&sW[p][kk][tm*4];
            float4 wB = *(const float4*)&sW[p][kk][tm*4+2];
            float4 aA = *(const float4*)&sA[p][kk][tn*4];
            float4 aB = *(const float4*)&sA[p][kk][tn*4+2];
            float wr[4] = {wA.x, wA.z, wB.x, wB.z};
            float wi[4] = {wA.y, wA.w, wB.y, wB.w};
            float xr[4] = {aA.x, aA.z, aB.x, aB.z};
            float xi[4] = {aA.y, aA.w, aB.y, aB.w};
            #pragma unroll
            for (int r = 0; r < 4; r++)
                #pragma unroll
                for (int c = 0; c < 4; c++) {
                    ar[r][c] += wr[r]*xr[c] - wi[r]*xi[c];
                    ai[r][c] += wr[r]*xi[c] + wi[r]*xr[c];
                }
        }
        if (pf) {
            int q = 1 - p;
            sW[q][wq0*2+0][wr0] = make_float2(w0v.x, w0v.y);
            sW[q][wq0*2+1][wr0] = make_float2(w0v.z, w0v.w);
            sW[q][wq1*2+0][wr1] = make_float2(w1v.x, w1v.y);
            sW[q][wq1*2+1][wr1] = make_float2(w1v.z, w1v.w);
            sA[q][ar0][aq0*2+0] = make_float2(a0v.x, a0v.y);
            sA[q][ar0][aq0*2+1] = make_float2(a0v.z, a0v.w);
            sA[q][ar1][aq1*2+0] = make_float2(a1v.x, a1v.y);
            sA[q][ar1][aq1*2+1] = make_float2(a1v.z, a1v.w);
        }
        __syncthreads();
    }
    int b = bc / 3, cc = bc % 3;
    #pragma unroll
    for (int r = 0; r < 4; r++)
        #pragma unroll
        for (int c = 0; c < 4; c++) {
            int gm = m0 + tm*4 + r, gn = n0 + tn*4 + c;
            if (gm >= LD) continue;
            float2 z = make_float2(ar[r][c], ai[r][c]);
            if (!CONJ) {
                if (gm < NDIM && gn < NH) {
                    float2 d = g_Dk[b*SZH + gm*LDH + gn];
                    float den = d.x*d.x + d.y*d.y + g_DgSum[cc*SZH + gm*LDH + gn];
                    float inv = 1.f / den;
                    float zr = (d.x*z.x + d.y*z.y) * inv;
                    float zi = (d.x*z.y - d.y*z.x) * inv;
                    z = make_float2(zr, zi);
                } else {
                    z = make_float2(0.f, 0.f);
                }
            }
            O[gm*LDH + gn] = z;
        }
}

// pass D: out[bc][m][j] = sum_n (Tr[m][n]*Wd[j][n].x + Ti[m][n]*Wd[j][n].y)
__global__ __launch_bounds__(256) void k_dft_rows_realout(float* __restrict__ out) {
    __shared__ __align__(16) float2 sT[2][GBK][64];
    __shared__ __align__(16) float2 sW[2][GBK][64];
    int bc = blockIdx.z, m0 = blockIdx.y*64, n0 = blockIdx.x*64;
    const float* Tf = (const float*)(g_C1 + bc*SZH);
    const float* Wdf = (const float*)g_Wd;
    int t = threadIdx.x, tm = t >> 4, tn = t & 15;
    int r0 = t >> 3,        q0 = t & 7;
    int r1 = (t+256) >> 3,  q1 = t & 7;
    float acc[4][4];
    #pragma unroll
    for (int r = 0; r < 4; r++)
        #pragma unroll
        for (int c = 0; c < 4; c++) acc[r][c] = 0.f;

    // preload tile 0
    {
        float4 t0 = make_float4(0.f,0.f,0.f,0.f);
        if (m0 + r0 < LD) t0 = *(const float4*)&Tf[(m0+r0)*(2*LDH) + q0*4];
        sT[0][q0*2+0][r0] = make_float2(t0.x, t0.y);
        sT[0][q0*2+1][r0] = make_float2(t0.z, t0.w);
        float4 t1 = make_float4(0.f,0.f,0.f,0.f);
        if (m0 + r1 < LD) t1 = *(const float4*)&Tf[(m0+r1)*(2*LDH) + q1*4];
        sT[0][q1*2+0][r1] = make_float2(t1.x, t1.y);
        sT[0][q1*2+1][r1] = make_float2(t1.z, t1.w);
        float4 w0 = make_float4(0.f,0.f,0.f,0.f);
        if (n0 + r0 < LD) w0 = *(const float4*)&Wdf[(n0+r0)*(2*LDH) + q0*4];
        sW[0][q0*2+0][r0] = make_float2(w0.x, w0.y);
        sW[0][q0*2+1][r0] = make_float2(w0.z, w0.w);
        float4 w1 = make_float4(0.f,0.f,0.f,0.f);
        if (n0 + r1 < LD) w1 = *(const float4*)&Wdf[(n0+r1)*(2*LDH) + q1*4];
        sW[0][q1*2+0][r1] = make_float2(w1.x, w1.y);
        sW[0][q1*2+1][r1] = make_float2(w1.z, w1.w);
    }
    __syncthreads();

    const int NIT = LDH/GBK;
    for (int it = 0; it < NIT; it++) {
        int p = it & 1;
        float4 t0v, t1v, w0v, w1v;
        bool pf = (it + 1 < NIT);
        if (pf) {
            int k0 = (it+1)*GBK;
            t0v = make_float4(0.f,0.f,0.f,0.f);
            if (m0 + r0 < LD) t0v = *(const float4*)&Tf[(m0+r0)*(2*LDH) + k0*2 + q0*4];
            t1v = make_float4(0.f,0.f,0.f,0.f);
            if (m0 + r1 < LD) t1v = *(const float4*)&Tf[(m0+r1)*(2*LDH) + k0*2 + q1*4];
            w0v = make_float4(0.f,0.f,0.f,0.f);
            if (n0 + r0 < LD) w0v = *(const float4*)&Wdf[(n0+r0)*(2*LDH) + k0*2 + q0*4];
            w1v = make_float4(0.f,0.f,0.f,0.f);
            if (n0 + r1 < LD) w1v = *(const float4*)&Wdf[(n0+r1)*(2*LDH) + k0*2 + q1*4];
        }
        #pragma unroll
        for (int kk = 0; kk < GBK; kk++) {
            float4 tA = *(const float4*)&sT[p][kk][tm*4];
            float4 tB = *(const float4*)&sT[p][kk][tm*4+2];
            float4 wA = *(const float4*)&sW[p][kk][tn*4];
            float4 wB = *(const float4*)&sW[p][kk][tn*4+2];
            float tr[4] = {tA.x, tA.z, tB.x, tB.z};
            float ti[4] = {tA.y, tA.w, tB.y, tB.w};
            float wr[4] = {wA.x, wA.z, wB.x, wB.z};
            float wi[4] = {wA.y, wA.w, wB.y, wB.w};
            #pragma unroll
            for (int r = 0; r < 4; r++)
                #pragma unroll
                for (int c = 0; c < 4; c++)
                    acc[r][c] += tr[r]*wr[c] + ti[r]*wi[c];
        }
        if (pf) {
            int q = 1 - p;
            sT[q][q0*2+0][r0] = make_float2(t0v.x, t0v.y);
            sT[q][q0*2+1][r0] = make_float2(t0v.z, t0v.w);
            sT[q][q1*2+0][r1] = make_float2(t1v.x, t1v.y);
            sT[q][q1*2+1][r1] = make_float2(t1v.z, t1v.w);
            sW[q][q0*2+0][r0] = make_float2(w0v.x, w0v.y);
            sW[q][q0*2+1][r0] = make_float2(w0v.z, w0v.w);
            sW[q][q1*2+0][r1] = make_float2(w1v.x, w1v.y);
            sW[q][q1*2+1][r1] = make_float2(w1v.z, w1v.w);
        }
        __syncthreads();
    }
    #pragma unroll
    for (int r = 0; r < 4; r++)
        #pragma unroll
        for (int c = 0; c < 4; c++) {
            int gm = m0 + tm*4 + r, gn = n0 + tn*4 + c;
            if (gm < NDIM && gn < NDIM)
                out[bc*NDIM*NDIM + gm*NDIM + gn] = acc[r][c];
        }
}

// ---------------- launch ----------------
extern "C" void kernel_launch(void* const* d_in, const int* in_sizes, int n_in,
                              void* d_out, int out_size) {
    const float* y    = (const float*)d_in[0];
    const float* kk   = (const float*)d_in[1];
    const float* lam  = (const float*)d_in[2];
    const float* filt = (const float*)d_in[3];
    float* out = (float*)d_out;

    k_wt<<<(NDIM+255)/256, 256>>>();
    k_wm<<<(SZ+255)/256, 256>>>();
    k_wd<<<(LD*LDH+255)/256, 256>>>();
    k_pad<<<(BC*SZ+255)/256, 256>>>(y);
    k_alpha<<<BB, 64>>>(kk);
    k_gb<<<(BB*NDIM*KS+127)/128, 128>>>(kk);
    k_dk<<<(BB*NDIM*NH+127)/128, 128>>>();
    k_dgsum<<<(CC*NDIM*NH+127)/128, 128>>>(filt, lam);

    dim3 cgrid(64, 1, BC), cblk(32, 8);
    k_conv<<<cgrid, cblk>>>(0, kk);   // xA -> xB (band)
    k_conv<<<cgrid, cblk>>>(1, kk);   // xB -> xA (band)
    k_conv<<<cgrid, cblk>>>(0, kk);   // xA -> xB (band, final)

    dim3 hgrid(5, 9, BC);
    k_dft_rows_realin<<<hgrid, 256>>>();          // xB -> C1   (row FFT, half-plane)
    k_dft_cols<false><<<hgrid, 256>>>();          // C1 -> C2   (col FFT + fused Wiener filter)
    k_dft_cols<true><<<hgrid, 256>>>();           // C2 -> C1   (col iFFT)
    dim3 dgrid(9, 9, BC);
    k_dft_rows_realout<<<dgrid, 256>>>(out);      // C1 -> out  (row iFFT, real)
}

// round 16
// speedup vs baseline: 1.2519x; 1.2519x over previous
#include <cuda_runtime.h>
#include <math.h>

#define NDIM 542
#define LD   544
#define SZ   (544*544)
#define LDH  320          // half-plane padded width (272 used)
#define NH   272          // 542/2 + 1
#define SZH  (544*320)
#define NHF  271          // 542/2
#define BB   8
#define CC   3
#define BC   24
#define KS   31
#define PAD  15
#define HREF 512

// ---------------- device scratch ----------------
__device__ __align__(16) float  g_xA[BC*SZ];
__device__ __align__(16) float  g_xB[BC*SZ];
__device__ __align__(16) float2 g_C1[BC*SZH];
__device__ __align__(16) float2 g_C2[BC*SZH];
__device__ __align__(16) float2 g_W[SZ];          // W[v*LD+j] = e^{-2i pi (v*j mod N)/N}, zero pads
__device__ __align__(16) float2 g_Wd[LD*LDH];     // Wd[j*LDH+n] = c_n/N^2 * e^{-2i pi (n*j mod N)/N}, zero pads
__device__ __align__(16) float2 g_W271[320*NH];   // W271[r*272+c] = e^{-2i pi (r*c mod 271)/271}, zero for r>=271 or c>=271
__device__ __align__(16) float2 g_Dk[BB*SZH];
__device__ float  g_DgSum[CC*SZH];
__device__ float2 g_Gb[BB*NDIM*KS];
__device__ float2 g_Wt[NDIM];
__device__ float  g_v[BB*2*NDIM];

// ---------------- twiddle tables ----------------
__global__ void k_wt() {
    int m = blockIdx.x*blockDim.x + threadIdx.x;
    if (m >= NDIM) return;
    float ang = (float)(-2.0*3.14159265358979323846/542.0) * (float)m;
    float s, c; sincosf(ang, &s, &c);
    g_Wt[m] = make_float2(c, s);
}

__global__ void k_wm() {
    int gid = blockIdx.x*blockDim.x + threadIdx.x;
    if (gid >= SZ) return;
    int v = gid / LD, j = gid % LD;
    float2 w = make_float2(0.f, 0.f);
    if (v < NDIM && j < NDIM) {
        int m = (v*j) % NDIM;
        float ang = (float)(-2.0*3.14159265358979323846/542.0) * (float)m;
        float s, c; sincosf(ang, &s, &c);
        w = make_float2(c, s);
    }
    g_W[gid] = w;
}

__global__ void k_wd() {
    int gid = blockIdx.x*blockDim.x + threadIdx.x;
    if (gid >= LD*LDH) return;
    int j = gid / LDH, n = gid % LDH;
    float2 w = make_float2(0.f, 0.f);
    if (j < NDIM && n < NH) {
        float cn = (n == 0 || n == NH-1) ? 1.f : 2.f;
        float scale = cn / ((float)NDIM * (float)NDIM);
        int m = (n * j) % NDIM;
        float2 t = g_Wt[m];
        w = make_float2(scale * t.x, scale * t.y);
    }
    g_Wd[gid] = w;
}

__global__ void k_w271() {
    int gid = blockIdx.x*blockDim.x + threadIdx.x;
    if (gid >= 320*NH) return;
    int r = gid / NH, c = gid % NH;
    float2 w = make_float2(0.f, 0.f);
    if (r < NHF && c < NHF) {
        int m = (r*c) % NHF;
        float ang = (float)(-2.0*3.14159265358979323846/271.0) * (float)m;
        float s, cs; sincosf(ang, &s, &cs);
        w = make_float2(cs, s);
    }
    g_W271[gid] = w;
}

// ---------------- edge-replicate pad (fills both ping-pong buffers) ----------------
__global__ void k_pad(const float* __restrict__ y) {
    int gid = blockIdx.x*blockDim.x + threadIdx.x;
    if (gid >= BC*SZ) return;
    int bc = gid / SZ, rem = gid % SZ, i = rem / LD, j = rem % LD;
    float val = 0.f;
    if (i < NDIM && j < NDIM) {
        int si = i - PAD; si = si < 0 ? 0 : (si > HREF-1 ? HREF-1 : si);
        int sj = j - PAD; sj = sj < 0 ? 0 : (sj > HREF-1 ? HREF-1 : sj);
        val = y[bc*HREF*HREF + si*HREF + sj];
    }
    g_xA[gid] = val;
    g_xB[gid] = val;
}

// ---------------- alpha (separable taper) ----------------
__global__ void k_alpha(const float* __restrict__ kptr) {
    int b = blockIdx.x;
    __shared__ float p[2][KS];
    __shared__ float rr[2][KS];
    int t = threadIdx.x; // 64 threads
    if (t < KS) {
        float s = 0.f;
        for (int j = 0; j < KS; j++) s += kptr[b*KS*KS + t*KS + j];
        p[0][t] = s;
    } else if (t >= 32 && t < 32+KS) {
        int c = t - 32; float s = 0.f;
        for (int i = 0; i < KS; i++) s += kptr[b*KS*KS + i*KS + c];
        p[1][c] = s;
    }
    __syncthreads();
    if (t < KS) {
        float s = 0.f;
        for (int n = 0; n + t < KS; n++) s += p[0][n]*p[0][n+t];
        rr[0][t] = s;
    } else if (t >= 32 && t < 32+KS) {
        int m = t - 32; float s = 0.f;
        for (int n = 0; n + m < KS; n++) s += p[1][n]*p[1][n+m];
        rr[1][m] = s;
    }
    __syncthreads();
    for (int i = t; i < NDIM; i += 64) {
        #pragma unroll
        for (int a = 0; a < 2; a++) {
            float z;
            if (i <= 30)                   z = rr[a][i];
            else if (i >= 511 && i <= 540) z = rr[a][541 - i];
            else if (i == 541)             z = rr[a][0];
            else                           z = 0.f;
            g_v[(b*2 + a)*NDIM + i] = 1.f - z / rr[a][0];
        }
    }
}

// ---------------- Dk: two-stage sparse DFT of k (half-plane in v) ----------------
__global__ void k_gb(const float* __restrict__ kptr) {
    int gid = blockIdx.x*blockDim.x + threadIdx.x;
    if (gid >= BB*NDIM*KS) return;
    int b = gid / (NDIM*KS), rem = gid % (NDIM*KS), u = rem / KS, j = rem % KS;
    int idx = (u * 527) % NDIM;
    float2 acc = make_float2(0.f, 0.f);
    for (int i = 0; i < KS; i++) {
        float kv = kptr[b*KS*KS + i*KS + j];
        float2 w = g_Wt[idx];
        acc.x += kv*w.x; acc.y += kv*w.y;
        idx += u; if (idx >= NDIM) idx -= NDIM;
    }
    g_Gb[gid] = acc;
}

__global__ void k_dk() {
    int gid = blockIdx.x*blockDim.x + threadIdx.x;
    if (gid >= BB*NDIM*NH) return;
    int b = gid / (NDIM*NH), rem = gid % (NDIM*NH), u = rem / NH, v = rem % NH;
    int idx = (v * 527) % NDIM;
    const float2* gb = &g_Gb[(b*NDIM + u)*KS];
    float2 acc = make_float2(0.f, 0.f);
    for (int j = 0; j < KS; j++) {
        float2 g = gb[j]; float2 w = g_Wt[idx];
        acc.x += g.x*w.x - g.y*w.y;
        acc.y += g.x*w.y + g.y*w.x;
        idx += v; if (idx >= NDIM) idx -= NDIM;
    }
    g_Dk[b*SZH + u*LDH + v] = acc;
}

// ---------------- DgSum (half-plane) ----------------
__global__ void k_dgsum(const float* __restrict__ filters, const float* __restrict__ lam) {
    int gid = blockIdx.x*blockDim.x + threadIdx.x;
    if (gid >= CC*NDIM*NH) return;
    int c = gid / (NDIM*NH), rem = gid % (NDIM*NH), u = rem / NH, v = rem % NH;
    float2 e[3][3];
    #pragma unroll
    for (int i = 0; i < 3; i++)
        #pragma unroll
        for (int j = 0; j < 3; j++) {
            int m = ((i-1)*u + (j-1)*v) % NDIM;
            if (m < 0) m += NDIM;
            e[i][j] = g_Wt[m];
        }
    float sum = 0.f;
    for (int nf = 0; nf < 8; nf++) {
        const float* f = &filters[(nf*CC + c)*9];
        float ax = 0.f, ay = 0.f;
        #pragma unroll
        for (int i = 0; i < 3; i++)
            #pragma unroll
            for (int j = 0; j < 3; j++) {
                float fv = f[i*3+j];
                ax += fv*e[i][j].x; ay += fv*e[i][j].y;
            }
        sum += ax*ax + ay*ay;
    }
    g_DgSum[c*SZH + u*LDH + v] = expf(lam[0]) * sum;
}

// ---------------- circular conv 31x31 + alpha blend (BAND ONLY) ----------------
__global__ __launch_bounds__(256) void k_conv(int dir, const float* __restrict__ kptr) {
    __shared__ float sk[KS*KS];
    __shared__ float sp[62*62];
    const float* in  = dir ? g_xB : g_xA;
    float*       out = dir ? g_xA : g_xB;
    int bc = blockIdx.z, b = bc / 3;
    int id = blockIdx.x;
    int bx0, by0;
    if (id < 17)      { by0 = 0;                  bx0 = id*32; }
    else if (id < 34) { by0 = 510;                bx0 = (id-17)*32; }
    else if (id < 49) { bx0 = 0;                  by0 = 32 + (id-34)*32; }
    else              { bx0 = 510;                by0 = 32 + (id-49)*32; }

    int tid = threadIdx.y*32 + threadIdx.x;
    for (int idx = tid; idx < KS*KS; idx += 256) sk[idx] = kptr[b*KS*KS + idx];
    const float* inb = in + bc*SZ;
    for (int idx = tid; idx < 62*62; idx += 256) {
        int r = idx / 62, c = idx % 62;
        int gi = by0 - PAD + r; if (gi < 0) gi += NDIM; else if (gi >= NDIM) gi -= NDIM;
        int gj = bx0 - PAD + c; if (gj < 0) gj += NDIM; else if (gj >= NDIM) gj -= NDIM;
        sp[idx] = inb[gi*LD + gj];
    }
    __syncthreads();
    int tx = threadIdx.x, ty = threadIdx.y;
    float acc[4] = {0.f, 0.f, 0.f, 0.f};
    for (int i = 0; i < KS; i++) {
        const float* p0 = &sp[(ty +  0 + 30 - i)*62 + tx + 30];
        const float* p1 = &sp[(ty +  8 + 30 - i)*62 + tx + 30];
        const float* p2 = &sp[(ty + 16 + 30 - i)*62 + tx + 30];
        const float* p3 = &sp[(ty + 24 + 30 - i)*62 + tx + 30];
        const float* pk = &sk[i*KS];
        #pragma unroll
        for (int j = 0; j < KS; j++) {
            float kv = pk[j];
            acc[0] += kv * p0[-j];
            acc[1] += kv * p1[-j];
            acc[2] += kv * p2[-j];
            acc[3] += kv * p3[-j];
        }
    }
    int x = bx0 + tx;
    float v1x = (x < NDIM) ? g_v[(b*2 + 1)*NDIM + x] : 0.f;
    float* outb = out + bc*SZ;
    #pragma unroll
    for (int r = 0; r < 4; r++) {
        int yy = by0 + ty + 8*r;
        if (yy < NDIM && x < NDIM) {
            float a  = g_v[(b*2 + 0)*NDIM + yy] * v1x;
            float c0 = sp[(ty + 8*r + 15)*62 + tx + 15];
            outb[yy*LD + x] = a*c0 + (1.f - a)*acc[r];
        }
    }
}

// ---------------- DFT GEMMs (single-buffered R9 style) ----------------
#define GBK 16

// pass A: C1[bc][m][n] = sum_k X[bc][m][k] * W[n][k],  n in [0,320)
__global__ __launch_bounds__(256) void k_dft_rows_realin() {
    __shared__ __align__(16) float  sX[GBK][64];
    __shared__ __align__(16) float2 sW[GBK][64];
    int bc = blockIdx.z, m0 = blockIdx.y*64, n0 = blockIdx.x*64;
    const float* Xb = g_xB + bc*SZ;
    const float* Wf = (const float*)g_W;
    int t = threadIdx.x, tm = t >> 4, tn = t & 15;
    float ar[4][4], ai[4][4];
    #pragma unroll
    for (int r = 0; r < 4; r++)
        #pragma unroll
        for (int c = 0; c < 4; c++) { ar[r][c] = 0.f; ai[r][c] = 0.f; }
    for (int k0 = 0; k0 < LD; k0 += GBK) {
        {
            int r = t >> 2, q = t & 3;
            float4 v = make_float4(0.f,0.f,0.f,0.f);
            if (m0 + r < LD) v = *(const float4*)&Xb[(m0+r)*LD + k0 + q*4];
            sX[q*4+0][r] = v.x; sX[q*4+1][r] = v.y; sX[q*4+2][r] = v.z; sX[q*4+3][r] = v.w;
        }
        #pragma unroll
        for (int s = 0; s < 2; s++) {
            int idx = t + s*256, r = idx >> 3, q = idx & 7;
            float4 v = *(const float4*)&Wf[(n0+r)*(2*LD) + k0*2 + q*4];   // n0+r < 320 < 542 always
            sW[q*2+0][r] = make_float2(v.x, v.y);
            sW[q*2+1][r] = make_float2(v.z, v.w);
        }
        __syncthreads();
        #pragma unroll
        for (int kk = 0; kk < GBK; kk++) {
            float4 a4 = *(const float4*)&sX[kk][tm*4];
            float4 wA = *(const float4*)&sW[kk][tn*4];
            float4 wB = *(const float4*)&sW[kk][tn*4+2];
            float a[4]  = {a4.x, a4.y, a4.z, a4.w};
            float wr[4] = {wA.x, wA.z, wB.x, wB.z};
            float wi[4] = {wA.y, wA.w, wB.y, wB.w};
            #pragma unroll
            for (int r = 0; r < 4; r++)
                #pragma unroll
                for (int c = 0; c < 4; c++) { ar[r][c] += a[r]*wr[c]; ai[r][c] += a[r]*wi[c]; }
        }
        __syncthreads();
    }
    float2* Ob = g_C1 + bc*SZH;
    #pragma unroll
    for (int r = 0; r < 4; r++)
        #pragma unroll
        for (int c = 0; c < 4; c++) {
            int gm = m0 + tm*4 + r, gn = n0 + tn*4 + c;
            if (gm < LD) Ob[gm*LDH + gn] = make_float2(ar[r][c], ai[r][c]);
        }
}

// ---------------- radix-2 butterfly: E/O formation (forward) ----------------
// C2[t][n]     = C1[t][n] + C1[t+271][n]
// C2[272+t][n] = (C1[t][n] - C1[t+271][n]) * w542^t
__global__ void k_eo() {
    int gid = blockIdx.x*blockDim.x + threadIdx.x;
    if (gid >= BC*NH*LDH) return;
    int bc = gid / (NH*LDH), rem = gid % (NH*LDH), t = rem / LDH, n = rem % LDH;
    float2* C2 = g_C2 + bc*SZH;
    if (t == NHF) {   // zero pad rows 271 and 543
        C2[NHF*LDH + n]      = make_float2(0.f, 0.f);
        C2[(NH+NHF)*LDH + n] = make_float2(0.f, 0.f);
        return;
    }
    const float2* C1 = g_C1 + bc*SZH;
    float2 F1 = C1[t*LDH + n];
    float2 F2 = C1[(t+NHF)*LDH + n];
    float2 E = make_float2(F1.x + F2.x, F1.y + F2.y);
    float2 d = make_float2(F1.x - F2.x, F1.y - F2.y);
    float2 w = g_Wt[t];
    float2 O = make_float2(d.x*w.x - d.y*w.y, d.x*w.y + d.y*w.x);
    C2[t*LDH + n]      = E;
    C2[(NH+t)*LDH + n] = O;
}

// ---------------- 271-point column GEMMs ----------------
// INV=false (fwd+Wiener): C1[half*272+t][n] = Filter_{m=2t+half}( sum_{m<272} W271[t][m] * C2[half*272+m][n] )
// INV=true  (inverse):    C2[half*272+t][n] = sum_{m<272} conj(W271[t][m]) * C1[half*272+m][n]
template<bool INV>
__global__ __launch_bounds__(256) void k_dft271() {
    __shared__ __align__(16) float2 sW[GBK][64];
    __shared__ __align__(16) float2 sA[GBK][64];
    int bc = blockIdx.z >> 1, half = blockIdx.z & 1;
    int m0 = blockIdx.y*64, n0 = blockIdx.x*64;
    const float2* A = (INV ? g_C1 : g_C2) + bc*SZH + half*NH*LDH;
    float2*       O = (INV ? g_C2 : g_C1) + bc*SZH + half*NH*LDH;
    const float* Wf = (const float*)g_W271;
    const float* Af = (const float*)A;
    int t = threadIdx.x, tm = t >> 4, tn = t & 15;
    float ar[4][4], ai[4][4];
    #pragma unroll
    for (int r = 0; r < 4; r++)
        #pragma unroll
        for (int c = 0; c < 4; c++) { ar[r][c] = 0.f; ai[r][c] = 0.f; }
    for (int k0 = 0; k0 < NH; k0 += GBK) {
        #pragma unroll
        for (int s = 0; s < 2; s++) {
            int idx = t + s*256, r = idx >> 3, q = idx & 7;
            float4 v = *(const float4*)&Wf[(m0+r)*(2*NH) + k0*2 + q*4];   // m0+r < 320: table rows valid
            if (INV) { v.y = -v.y; v.w = -v.w; }
            sW[q*2+0][r] = make_float2(v.x, v.y);
            sW[q*2+1][r] = make_float2(v.z, v.w);
        }
        #pragma unroll
        for (int s = 0; s < 2; s++) {
            int idx = t + s*256, r = idx >> 5, q = idx & 31;
            float4 v = *(const float4*)&Af[(k0+r)*(2*LDH) + (n0 + q*2)*2];  // k0+r <= 271
            sA[r][q*2+0] = make_float2(v.x, v.y);
            sA[r][q*2+1] = make_float2(v.z, v.w);
        }
        __syncthreads();
        #pragma unroll
        for (int kk = 0; kk < GBK; kk++) {
            float4 wA = *(const float4*)&sW[kk][tm*4];
            float4 wB = *(const float4*)&sW[kk][tm*4+2];
            float4 aA = *(const float4*)&sA[kk][tn*4];
            float4 aB = *(const float4*)&sA[kk][tn*4+2];
            float wr[4] = {wA.x, wA.z, wB.x, wB.z};
            float wi[4] = {wA.y, wA.w, wB.y, wB.w};
            float xr[4] = {aA.x, aA.z, aB.x, aB.z};
            float xi[4] = {aA.y, aA.w, aB.y, aB.w};
            #pragma unroll
            for (int r = 0; r < 4; r++)
                #pragma unroll
                for (int c = 0; c < 4; c++) {
                    ar[r][c] += wr[r]*xr[c] - wi[r]*xi[c];
                    ai[r][c] += wr[r]*xi[c] + wi[r]*xr[c];
                }
        }
        __syncthreads();
    }
    int b = bc / 3, cc = bc % 3;
    #pragma unroll
    for (int r = 0; r < 4; r++)
        #pragma unroll
        for (int c = 0; c < 4; c++) {
            int gm = m0 + tm*4 + r, gn = n0 + tn*4 + c;
            if (gm >= NH) continue;         // never touch the other half's rows
            float2 z = make_float2(ar[r][c], ai[r][c]);
            if (!INV) {
                // fused Wiener filter at actual frequency row m = 2*gm + half
                if (gm < NHF && gn < NH) {
                    int m_act = 2*gm + half;
                    float2 d = g_Dk[b*SZH + m_act*LDH + gn];
                    float den = d.x*d.x + d.y*d.y + g_DgSum[cc*SZH + m_act*LDH + gn];
                    float inv = 1.f / den;
                    float zr = (d.x*z.x + d.y*z.y) * inv;
                    float zi = (d.x*z.y - d.y*z.x) * inv;
                    z = make_float2(zr, zi);
                } else {
                    z = make_float2(0.f, 0.f);
                }
            }
            O[gm*LDH + gn] = z;
        }
}

// ---------------- radix-2 recombine (inverse) ----------------
// T[m'][n]     = P[m'][n] + conj(w542^m') * Q[m'][n]
// T[m'+271][n] = P[m'][n] - conj(w542^m') * Q[m'][n]
__global__ void k_comb() {
    int gid = blockIdx.x*blockDim.x + threadIdx.x;
    if (gid >= BC*NH*LDH) return;
    int bc = gid / (NH*LDH), rem = gid % (NH*LDH), m = rem / LDH, n = rem % LDH;
    float2* C1 = g_C1 + bc*SZH;
    if (m == NHF) {   // zero pad rows 542, 543
        C1[NDIM*LDH + n]     = make_float2(0.f, 0.f);
        C1[(NDIM+1)*LDH + n] = make_float2(0.f, 0.f);
        return;
    }
    const float2* C2 = g_C2 + bc*SZH;
    float2 P = C2[m*LDH + n];
    float2 Q = C2[(NH+m)*LDH + n];
    float2 w = g_Wt[m];   // c = conj(w)
    float2 cQ = make_float2(w.x*Q.x + w.y*Q.y, w.x*Q.y - w.y*Q.x);
    C1[m*LDH + n]       = make_float2(P.x + cQ.x, P.y + cQ.y);
    C1[(m+NHF)*LDH + n] = make_float2(P.x - cQ.x, P.y - cQ.y);
}

// pass D: out[bc][m][j] = sum_n (Tr[m][n]*Wd[j][n].x + Ti[m][n]*Wd[j][n].y)
__global__ __launch_bounds__(256) void k_dft_rows_realout(float* __restrict__ out) {
    __shared__ __align__(16) float2 sT[GBK][64];
    __shared__ __align__(16) float2 sW[GBK][64];
    int bc = blockIdx.z, m0 = blockIdx.y*64, n0 = blockIdx.x*64;   // n0 = j tile
    const float* Tf = (const float*)(g_C1 + bc*SZH);
    const float* Wdf = (const float*)g_Wd;
    int t = threadIdx.x, tm = t >> 4, tn = t & 15;
    float acc[4][4];
    #pragma unroll
    for (int r = 0; r < 4; r++)
        #pragma unroll
        for (int c = 0; c < 4; c++) acc[r][c] = 0.f;
    for (int k0 = 0; k0 < LDH; k0 += GBK) {
        #pragma unroll
        for (int s = 0; s < 2; s++) {
            int idx = t + s*256, r = idx >> 3, q = idx & 7;
            float4 v = make_float4(0.f,0.f,0.f,0.f);
            if (m0 + r < LD) v = *(const float4*)&Tf[(m0+r)*(2*LDH) + k0*2 + q*4];
            sT[q*2+0][r] = make_float2(v.x, v.y);
            sT[q*2+1][r] = make_float2(v.z, v.w);
        }
        #pragma unroll
        for (int s = 0; s < 2; s++) {
            int idx = t + s*256, r = idx >> 3, q = idx & 7;
            float4 v = make_float4(0.f,0.f,0.f,0.f);
            if (n0 + r < LD) v = *(const float4*)&Wdf[(n0+r)*(2*LDH) + k0*2 + q*4];
            sW[q*2+0][r] = make_float2(v.x, v.y);
            sW[q*2+1][r] = make_float2(v.z, v.w);
        }
        __syncthreads();
        #pragma unroll
        for (int kk = 0; kk < GBK; kk++) {
            float4 tA = *(const float4*)&sT[kk][tm*4];
            float4 tB = *(const float4*)&sT[kk][tm*4+2];
            float4 wA = *(const float4*)&sW[kk][tn*4];
            float4 wB = *(const float4*)&sW[kk][tn*4+2];
            float tr[4] = {tA.x, tA.z, tB.x, tB.z};
            float ti[4] = {tA.y, tA.w, tB.y, tB.w};
            float wr[4] = {wA.x, wA.z, wB.x, wB.z};
            float wi[4] = {wA.y, wA.w, wB.y, wB.w};
            #pragma unroll
            for (int r = 0; r < 4; r++)
                #pragma unroll
                for (int c = 0; c < 4; c++)
                    acc[r][c] += tr[r]*wr[c] + ti[r]*wi[c];
        }
        __syncthreads();
    }
    #pragma unroll
    for (int r = 0; r < 4; r++)
        #pragma unroll
        for (int c = 0; c < 4; c++) {
            int gm = m0 + tm*4 + r, gn = n0 + tn*4 + c;
            if (gm < NDIM && gn < NDIM)
                out[bc*NDIM*NDIM + gm*NDIM + gn] = acc[r][c];
        }
}

// ---------------- launch ----------------
extern "C" void kernel_launch(void* const* d_in, const int* in_sizes, int n_in,
                              void* d_out, int out_size) {
    const float* y    = (const float*)d_in[0];
    const float* kk   = (const float*)d_in[1];
    const float* lam  = (const float*)d_in[2];
    const float* filt = (const float*)d_in[3];
    float* out = (float*)d_out;

    k_wt<<<(NDIM+255)/256, 256>>>();
    k_wm<<<(SZ+255)/256, 256>>>();
    k_wd<<<(LD*LDH+255)/256, 256>>>();
    k_w271<<<(320*NH+255)/256, 256>>>();
    k_pad<<<(BC*SZ+255)/256, 256>>>(y);
    k_alpha<<<BB, 64>>>(kk);
    k_gb<<<(BB*NDIM*KS+127)/128, 128>>>(kk);
    k_dk<<<(BB*NDIM*NH+127)/128, 128>>>();
    k_dgsum<<<(CC*NDIM*NH+127)/128, 128>>>(filt, lam);

    dim3 cgrid(64, 1, BC), cblk(32, 8);
    k_conv<<<cgrid, cblk>>>(0, kk);   // xA -> xB (band)
    k_conv<<<cgrid, cblk>>>(1, kk);   // xB -> xA (band)
    k_conv<<<cgrid, cblk>>>(0, kk);   // xA -> xB (band, final)

    dim3 hgrid(5, 9, BC);
    k_dft_rows_realin<<<hgrid, 256>>>();          // xB -> C1   (row FFT, half-plane)
    k_eo<<<(BC*NH*LDH+255)/256, 256>>>();         // C1 -> C2   (radix-2 E/O)
    dim3 ggrid(5, 5, BC*2);
    k_dft271<false><<<ggrid, 256>>>();            // C2 -> C1   (271-pt col FFT ×2 + fused Wiener)
    k_dft271<true><<<ggrid, 256>>>();             // C1 -> C2   (271-pt col iFFT ×2)
    k_comb<<<(BC*NH*LDH+255)/256, 256>>>();       // C2 -> C1   (radix-2 recombine)
    dim3 dgrid(9, 9, BC);
    k_dft_rows_realout<<<dgrid, 256>>>(out);      // C1 -> out  (row iFFT, real)
}